// round 15
// baseline (speedup 1.0000x reference)
#include <cuda_runtime.h>
#include <cuda_fp16.h>
#include <cstdint>

#define NN 100000
#define EE 1000000
#define RR 1000
#define DD 100
#define D4 25
#define FH 256      // halfs per feat row: 128 (E, padded) + 128 (R, padded)
#define NBIN 64

// ---------------- device scratch (static; no allocations) ------------------
__device__ int    g_row_ptr[NN + 1];
__device__ int    g_bins[NBIN];              // degree histogram
__device__ int    g_binoff[NBIN];            // exclusive offsets (mutated by scatter)
__device__ int    g_perm[NN];                // degree-sorted node order
__device__ __half g_relH[RR * 128];          // normalized rel embeddings, fp16, padded
__device__ float4 g_relsc[2][RR];            // (-2rwE, rrE, -2rwR, rrR) per layer
__device__ float2 g_nd[2][NN];               // (ndotE, ndotR) per layer parity
__device__ __half g_featH0[(size_t)NN * FH]; // fp16 feature tables (51.2MB each)
__device__ __half g_featH1[(size_t)NN * FH];

// ---------------------------------------------------------------------------
__device__ __forceinline__ void wred2(float& a, float& b) {
#pragma unroll
    for (int o = 16; o; o >>= 1) {
        a += __shfl_xor_sync(0xffffffffu, a, o);
        b += __shfl_xor_sync(0xffffffffu, b, o);
    }
}
__device__ __forceinline__ float dot4(float4 a, float4 b) {
    return a.x * b.x + a.y * b.y + a.z * b.z + a.w * b.w;
}
__device__ __forceinline__ void h8f(uint4 h, float* f) {
    float2 t;
    t = __half22float2(*reinterpret_cast<__half2*>(&h.x)); f[0] = t.x; f[1] = t.y;
    t = __half22float2(*reinterpret_cast<__half2*>(&h.y)); f[2] = t.x; f[3] = t.y;
    t = __half22float2(*reinterpret_cast<__half2*>(&h.z)); f[4] = t.x; f[5] = t.y;
    t = __half22float2(*reinterpret_cast<__half2*>(&h.w)); f[6] = t.x; f[7] = t.y;
}
__device__ __forceinline__ uint4 f8h(const float* f) {
    uint4 r; __half2 h;
    h = __floats2half2_rn(f[0], f[1]); r.x = *reinterpret_cast<unsigned*>(&h);
    h = __floats2half2_rn(f[2], f[3]); r.y = *reinterpret_cast<unsigned*>(&h);
    h = __floats2half2_rn(f[4], f[5]); r.z = *reinterpret_cast<unsigned*>(&h);
    h = __floats2half2_rn(f[6], f[7]); r.w = *reinterpret_cast<unsigned*>(&h);
    return r;
}

// ---------------- K0: row_ptr from sorted dst (+ zero bins) ----------------
__global__ void k_rowptr(const int* __restrict__ dst) {
    int n = blockIdx.x * blockDim.x + threadIdx.x;
    if (blockIdx.x == 0 && threadIdx.x < NBIN) g_bins[threadIdx.x] = 0;
    if (n > NN) return;
    int lo = 0, hi = EE;
    while (lo < hi) {
        int mid = (lo + hi) >> 1;
        if (dst[mid] < n) lo = mid + 1; else hi = mid;
    }
    g_row_ptr[n] = lo;
}

// ---------------- K0b/c/d: degree-sorted permutation -----------------------
__global__ void k_hist() {
    int n = blockIdx.x * blockDim.x + threadIdx.x;
    if (n >= NN) return;
    int deg = min(g_row_ptr[n + 1] - g_row_ptr[n], NBIN - 1);
    atomicAdd(&g_bins[deg], 1);
}
__global__ void k_scan() {
    if (threadIdx.x == 0) {
        int run = 0;
        for (int i = 0; i < NBIN; i++) { g_binoff[i] = run; run += g_bins[i]; }
    }
}
__global__ void k_scatter() {
    int n = blockIdx.x * blockDim.x + threadIdx.x;
    if (n >= NN) return;
    int deg = min(g_row_ptr[n + 1] - g_row_ptr[n], NBIN - 1);
    int pos = atomicAdd(&g_binoff[deg], 1);
    g_perm[pos] = n;
}

// ---------------- K1: relation normalization + per-relation scalars --------
__global__ void k_rel(const float* __restrict__ rel_emb,
                      const float* __restrict__ attn_e,
                      const float* __restrict__ attn_r) {
    int warp = (blockIdx.x * blockDim.x + threadIdx.x) >> 5;
    int lane = threadIdx.x & 31;
    if (warp >= RR) return;

    float4 v = {0.f, 0.f, 0.f, 0.f};
    if (lane < D4) v = reinterpret_cast<const float4*>(rel_emb)[warp * D4 + lane];
    float ss = dot4(v, v), dummy = 0.f;
    wred2(ss, dummy);
    float inv = 1.f / fmaxf(sqrtf(ss), 1e-12f);
    v.x *= inv; v.y *= inv; v.z *= inv; v.w *= inv;
    {
        __half2 h0 = __floats2half2_rn(v.x, v.y), h1 = __floats2half2_rn(v.z, v.w);
        uint2 p; p.x = *reinterpret_cast<unsigned*>(&h0); p.y = *reinterpret_cast<unsigned*>(&h1);
        reinterpret_cast<uint2*>(g_relH + warp * 128)[lane] = p;
    }

#pragma unroll
    for (int c = 0; c < 4; c++) {
        const float* attn = (c < 2 ? attn_e : attn_r) + (c & 1) * (3 * DD);
        float4 wn = {0,0,0,0}, wr = {0,0,0,0};
        if (lane < D4) {
            wn = reinterpret_cast<const float4*>(attn + DD)[lane];
            wr = reinterpret_cast<const float4*>(attn + 2 * DD)[lane];
        }
        float dn = dot4(v, wn);
        float dr = dot4(v, wr);
        wred2(dn, dr);
        if (lane == 0) {
            int layer = c & 1;
            if (c < 2) { g_relsc[layer][warp].x = -2.f * dn; g_relsc[layer][warp].y = dr; }
            else       { g_relsc[layer][warp].z = -2.f * dn; g_relsc[layer][warp].w = dr; }
        }
    }
}

// ---------------- K2: initial segment means + tanh + ndot(layer 0) ---------
__global__ void __launch_bounds__(256)
k_init(const float* __restrict__ ent_emb,
       const float* __restrict__ rel_emb,
       const int* __restrict__ src,
       const int* __restrict__ erel,
       const float* __restrict__ attn_e,
       const float* __restrict__ attn_r,
       float* __restrict__ out) {
    int wi = (blockIdx.x * blockDim.x + threadIdx.x) >> 5;
    int lane = threadIdx.x & 31;
    if (wi >= NN) return;
    int node = g_perm[wi];
    int beg = g_row_ptr[node], end = g_row_ptr[node + 1];
    bool act = lane < D4;

    const float4* ent4 = reinterpret_cast<const float4*>(ent_emb);
    const float4* rel4 = reinterpret_cast<const float4*>(rel_emb);
    float4 aE = {0,0,0,0}, aR = {0,0,0,0};
    float4 bE = {0,0,0,0}, bR = {0,0,0,0};
    int e = beg;
    for (; e + 3 < end; e += 4) {
        int s0 = src[e],   r0 = erel[e];
        int s1 = src[e+1], r1 = erel[e+1];
        int s2 = src[e+2], r2 = erel[e+2];
        int s3 = src[e+3], r3 = erel[e+3];
        if (act) {
            float4 a0 = ent4[s0*D4+lane], c0 = rel4[r0*D4+lane];
            float4 a1 = ent4[s1*D4+lane], c1 = rel4[r1*D4+lane];
            float4 a2 = ent4[s2*D4+lane], c2 = rel4[r2*D4+lane];
            float4 a3 = ent4[s3*D4+lane], c3 = rel4[r3*D4+lane];
            aE.x += a0.x + a1.x; aE.y += a0.y + a1.y; aE.z += a0.z + a1.z; aE.w += a0.w + a1.w;
            bE.x += a2.x + a3.x; bE.y += a2.y + a3.y; bE.z += a2.z + a3.z; bE.w += a2.w + a3.w;
            aR.x += c0.x + c1.x; aR.y += c0.y + c1.y; aR.z += c0.z + c1.z; aR.w += c0.w + c1.w;
            bR.x += c2.x + c3.x; bR.y += c2.y + c3.y; bR.z += c2.z + c3.z; bR.w += c2.w + c3.w;
        }
    }
    for (; e < end; e++) {
        int s0 = src[e], r0 = erel[e];
        if (act) {
            float4 a0 = ent4[s0*D4+lane], c0 = rel4[r0*D4+lane];
            aE.x += a0.x; aE.y += a0.y; aE.z += a0.z; aE.w += a0.w;
            aR.x += c0.x; aR.y += c0.y; aR.z += c0.z; aR.w += c0.w;
        }
    }
    aE.x += bE.x; aE.y += bE.y; aE.z += bE.z; aE.w += bE.w;
    aR.x += bR.x; aR.y += bR.y; aR.z += bR.z; aR.w += bR.w;

    float inv = 1.f / (float)max(end - beg, 1);
    float4 fE, fR;   // non-act lanes: zeros -> fp16 padding stays zero
    fE.x = tanhf(aE.x * inv); fE.y = tanhf(aE.y * inv);
    fE.z = tanhf(aE.z * inv); fE.w = tanhf(aE.w * inv);
    fR.x = tanhf(aR.x * inv); fR.y = tanhf(aR.y * inv);
    fR.z = tanhf(aR.z * inv); fR.w = tanhf(aR.w * inv);

    {
        __half* row = g_featH0 + (size_t)node * FH;
        __half2 h0 = __floats2half2_rn(fE.x, fE.y), h1 = __floats2half2_rn(fE.z, fE.w);
        uint2 p; p.x = *reinterpret_cast<unsigned*>(&h0); p.y = *reinterpret_cast<unsigned*>(&h1);
        reinterpret_cast<uint2*>(row)[lane] = p;
        h0 = __floats2half2_rn(fR.x, fR.y); h1 = __floats2half2_rn(fR.z, fR.w);
        p.x = *reinterpret_cast<unsigned*>(&h0); p.y = *reinterpret_cast<unsigned*>(&h1);
        reinterpret_cast<uint2*>(row + 128)[lane] = p;
    }

    float4* out4 = reinterpret_cast<float4*>(out);
    if (act) {
        __stcs(out4 + (size_t)node * 150 + lane, fE);
        __stcs(out4 + (size_t)node * 150 + 75 + lane, fR);
    }

    float4 wnE = {0,0,0,0}, wnR = {0,0,0,0};
    if (act) {
        wnE = reinterpret_cast<const float4*>(attn_e + DD)[lane];
        wnR = reinterpret_cast<const float4*>(attn_r + DD)[lane];
    }
    float dE = dot4(fE, wnE);
    float dR = dot4(fR, wnR);
    wred2(dE, dR);
    if (lane == 0) g_nd[0][node] = make_float2(dE, dR);
}

// ---------------- K3: attention layer, fp16 gathers, 16-lane groups --------
template <int LAYER>
__global__ void __launch_bounds__(256)
k_layer(const int* __restrict__ src,
        const int* __restrict__ erel,
        const float* __restrict__ attn_e,
        const float* __restrict__ attn_r,
        float* __restrict__ out) {
    int wi = (blockIdx.x * blockDim.x + threadIdx.x) >> 5;
    int lane = threadIdx.x & 31;
    if (wi >= NN) return;
    int node = g_perm[wi];
    int beg = g_row_ptr[node], end = g_row_ptr[node + 1];
    int len = end - beg;

    const __half* __restrict__ feat = (LAYER == 0) ? g_featH0 : g_featH1;
    const float2* __restrict__ nd   = g_nd[LAYER];
    const float4* __restrict__ rsc  = g_relsc[LAYER];

    int gid = lane >> 4;          // edge slot within pair
    int k   = lane & 15;          // half-chunk: dims [8k, 8k+8)

    float ZE = 0.f, ZR = 0.f;
    float accE[8] = {0,0,0,0,0,0,0,0};
    float accR[8] = {0,0,0,0,0,0,0,0};

    int niter = (len + 1) >> 1;
    for (int it = 0; it < niter; it++) {
        int e = beg + 2 * it + gid;
        bool valid = e < end;
        int ec = valid ? e : end - 1;
        int s = src[ec], r = erel[ec];

        const uint4* frow = reinterpret_cast<const uint4*>(feat + (size_t)s * FH);
        uint4 hE = frow[k];
        uint4 hR = frow[16 + k];
        uint4 hV = reinterpret_cast<const uint4*>(g_relH + r * 128)[k];
        float2 ndv = nd[s];
        float4 sc  = rsc[r];

        float fE[8], fR[8], rv[8];
        h8f(hE, fE); h8f(hR, fR); h8f(hV, rv);

        float pE = fE[0] * rv[0], pR = fR[0] * rv[0];
#pragma unroll
        for (int i = 1; i < 8; i++) {
            pE = fmaf(fE[i], rv[i], pE);
            pR = fmaf(fR[i], rv[i], pR);
        }
#pragma unroll
        for (int o = 1; o <= 8; o <<= 1) {
            pE += __shfl_xor_sync(0xffffffffu, pE, o);
            pR += __shfl_xor_sync(0xffffffffu, pR, o);
        }

        float wE = valid ? __expf(ndv.x + fmaf(pE, sc.x, sc.y)) : 0.f;
        float wR = valid ? __expf(ndv.y + fmaf(pR, sc.z, sc.w)) : 0.f;
        ZE += wE; ZR += wR;
        float bE = 2.f * wE * pE, bR = 2.f * wR * pR;

#pragma unroll
        for (int i = 0; i < 8; i++) {
            accE[i] = fmaf(wE, fE[i], fmaf(-bE, rv[i], accE[i]));
            accR[i] = fmaf(wR, fR[i], fmaf(-bR, rv[i], accR[i]));
        }
    }

    // cross-group combine: lanes l and l+16 end with identical chunk-k totals
    ZE += __shfl_xor_sync(0xffffffffu, ZE, 16);
    ZR += __shfl_xor_sync(0xffffffffu, ZR, 16);
#pragma unroll
    for (int i = 0; i < 8; i++) {
        accE[i] += __shfl_xor_sync(0xffffffffu, accE[i], 16);
        accR[i] += __shfl_xor_sync(0xffffffffu, accR[i], 16);
    }

    float oE[8], oR[8];
    if (len > 0) {
        float izE = 1.f / ZE, izR = 1.f / ZR;
#pragma unroll
        for (int i = 0; i < 8; i++) {
            oE[i] = tanhf(accE[i] * izE);   // padding dims: acc==0 -> 0
            oR[i] = tanhf(accR[i] * izR);
        }
    } else {
#pragma unroll
        for (int i = 0; i < 8; i++) { oE[i] = 0.f; oR[i] = 0.f; }
    }

    // fp32 output: lanes<16 write E chunks, lanes>=16 write R chunks (no dup)
    float4* out4 = reinterpret_cast<float4*>(out);
    {
        const float* o8 = gid ? oR : oE;
        size_t base = (size_t)node * 150 + (LAYER + 1) * D4 + (gid ? 75 : 0);
        float4 lo = {o8[0], o8[1], o8[2], o8[3]};
        float4 hi = {o8[4], o8[5], o8[6], o8[7]};
        int f0 = 2 * k, f1 = 2 * k + 1;
        if (f0 < D4) __stcs(out4 + base + f0, lo);
        if (f1 < D4) __stcs(out4 + base + f1, hi);
    }

    if (LAYER == 0) {
        // fp16 feat1 store: lanes<16 store E chunk k, lanes>=16 store R chunk k
        __half* row = g_featH1 + (size_t)node * FH;
        uint4 packed = f8h(gid ? oR : oE);
        reinterpret_cast<uint4*>(row)[gid * 16 + k] = packed;

        // ndot for layer 1 (padding dims of oE/oR are exact zeros)
        const float* wnE = attn_e + 3 * DD + DD;
        const float* wnR = attn_r + 3 * DD + DD;
        float4 wa = reinterpret_cast<const float4*>(wnE + 8 * k)[0];
        float4 wb = reinterpret_cast<const float4*>(wnE + 8 * k)[1];
        float dE = oE[0]*wa.x + oE[1]*wa.y + oE[2]*wa.z + oE[3]*wa.w
                 + oE[4]*wb.x + oE[5]*wb.y + oE[6]*wb.z + oE[7]*wb.w;
        wa = reinterpret_cast<const float4*>(wnR + 8 * k)[0];
        wb = reinterpret_cast<const float4*>(wnR + 8 * k)[1];
        float dR = oR[0]*wa.x + oR[1]*wa.y + oR[2]*wa.z + oR[3]*wa.w
                 + oR[4]*wb.x + oR[5]*wb.y + oR[6]*wb.z + oR[7]*wb.w;
#pragma unroll
        for (int o = 1; o <= 8; o <<= 1) {
            dE += __shfl_xor_sync(0xffffffffu, dE, o);
            dR += __shfl_xor_sync(0xffffffffu, dR, o);
        }
        if (lane == 0) g_nd[1][node] = make_float2(dE, dR);
    }
}

// ---------------------------------------------------------------------------
extern "C" void kernel_launch(void* const* d_in, const int* in_sizes, int n_in,
                              void* d_out, int out_size) {
    const float* ent_emb = (const float*)d_in[0];
    const float* rel_emb = (const float*)d_in[1];
    const float* attn_e  = (const float*)d_in[2];
    const float* attn_r  = (const float*)d_in[3];
    const int*   src     = (const int*)d_in[4];
    const int*   dst     = (const int*)d_in[5];
    const int*   erel    = (const int*)d_in[6];
    float* out = (float*)d_out;

    k_rowptr<<<(NN + 1 + 255) / 256, 256>>>(dst);
    k_hist<<<(NN + 255) / 256, 256>>>();
    k_scan<<<1, 32>>>();
    k_scatter<<<(NN + 255) / 256, 256>>>();
    k_rel<<<(RR * 32 + 255) / 256, 256>>>(rel_emb, attn_e, attn_r);
    k_init<<<(NN * 32) / 256, 256>>>(ent_emb, rel_emb, src, erel,
                                     attn_e, attn_r, out);
    k_layer<0><<<(NN * 32) / 256, 256>>>(src, erel, attn_e, attn_r, out);
    k_layer<1><<<(NN * 32) / 256, 256>>>(src, erel, attn_e, attn_r, out);
}

// round 16
// speedup vs baseline: 1.0953x; 1.0953x over previous
#include <cuda_runtime.h>
#include <cuda_fp16.h>
#include <cstdint>

#define NN 100000
#define EE 1000000
#define RR 1000
#define DD 100
#define D4 25
#define FH 256      // halfs per feat row: 128 (E, padded) + 128 (R, padded)

// ---------------- device scratch (static; no allocations) ------------------
__device__ int    g_row_ptr[NN + 1];
__device__ __half g_entH[(size_t)NN * 128];  // fp16 ent_emb, padded (25.6MB)
__device__ __half g_relEH[RR * 128];         // fp16 rel_emb (unnormalized), padded
__device__ __half g_relH[RR * 128];          // normalized rel embeddings, fp16, padded
__device__ float4 g_relsc[2][RR];            // (-2rwE, rrE, -2rwR, rrR) per layer
__device__ float2 g_nd[2][NN];               // (ndotE, ndotR) per layer parity
__device__ __half g_featH0[(size_t)NN * FH]; // fp16 feature tables (51.2MB each)
__device__ __half g_featH1[(size_t)NN * FH];

// ---------------------------------------------------------------------------
__device__ __forceinline__ void wred2(float& a, float& b) {
#pragma unroll
    for (int o = 16; o; o >>= 1) {
        a += __shfl_xor_sync(0xffffffffu, a, o);
        b += __shfl_xor_sync(0xffffffffu, b, o);
    }
}
__device__ __forceinline__ float dot4(float4 a, float4 b) {
    return a.x * b.x + a.y * b.y + a.z * b.z + a.w * b.w;
}
__device__ __forceinline__ void h8f(uint4 h, float* f) {
    float2 t;
    t = __half22float2(*reinterpret_cast<__half2*>(&h.x)); f[0] = t.x; f[1] = t.y;
    t = __half22float2(*reinterpret_cast<__half2*>(&h.y)); f[2] = t.x; f[3] = t.y;
    t = __half22float2(*reinterpret_cast<__half2*>(&h.z)); f[4] = t.x; f[5] = t.y;
    t = __half22float2(*reinterpret_cast<__half2*>(&h.w)); f[6] = t.x; f[7] = t.y;
}
__device__ __forceinline__ uint4 f8h(const float* f) {
    uint4 r; __half2 h;
    h = __floats2half2_rn(f[0], f[1]); r.x = *reinterpret_cast<unsigned*>(&h);
    h = __floats2half2_rn(f[2], f[3]); r.y = *reinterpret_cast<unsigned*>(&h);
    h = __floats2half2_rn(f[4], f[5]); r.z = *reinterpret_cast<unsigned*>(&h);
    h = __floats2half2_rn(f[6], f[7]); r.w = *reinterpret_cast<unsigned*>(&h);
    return r;
}

// ---------------- K0: row_ptr from sorted dst ------------------------------
__global__ void k_rowptr(const int* __restrict__ dst) {
    int n = blockIdx.x * blockDim.x + threadIdx.x;
    if (n > NN) return;
    int lo = 0, hi = EE;
    while (lo < hi) {
        int mid = (lo + hi) >> 1;
        if (dst[mid] < n) lo = mid + 1; else hi = mid;
    }
    g_row_ptr[n] = lo;
}

// ---------------- K0b: fp16-convert ent_emb / rel_emb (padded rows) --------
__global__ void k_cvt(const float* __restrict__ ent_emb,
                      const float* __restrict__ rel_emb) {
    int warp = (blockIdx.x * blockDim.x + threadIdx.x) >> 5;
    int lane = threadIdx.x & 31;
    const float4* srcr; __half* dstr;
    if (warp < NN)           { srcr = reinterpret_cast<const float4*>(ent_emb) + (size_t)warp * D4; dstr = g_entH + (size_t)warp * 128; }
    else if (warp < NN + RR) { srcr = reinterpret_cast<const float4*>(rel_emb) + (size_t)(warp - NN) * D4; dstr = g_relEH + (size_t)(warp - NN) * 128; }
    else return;
    float4 v = {0,0,0,0};
    if (lane < D4) v = srcr[lane];
    __half2 h0 = __floats2half2_rn(v.x, v.y), h1 = __floats2half2_rn(v.z, v.w);
    uint2 p; p.x = *reinterpret_cast<unsigned*>(&h0); p.y = *reinterpret_cast<unsigned*>(&h1);
    reinterpret_cast<uint2*>(dstr)[lane] = p;
}

// ---------------- K1: relation normalization + per-relation scalars --------
__global__ void k_rel(const float* __restrict__ rel_emb,
                      const float* __restrict__ attn_e,
                      const float* __restrict__ attn_r) {
    int warp = (blockIdx.x * blockDim.x + threadIdx.x) >> 5;
    int lane = threadIdx.x & 31;
    if (warp >= RR) return;

    float4 v = {0.f, 0.f, 0.f, 0.f};
    if (lane < D4) v = reinterpret_cast<const float4*>(rel_emb)[warp * D4 + lane];
    float ss = dot4(v, v), dummy = 0.f;
    wred2(ss, dummy);
    float inv = 1.f / fmaxf(sqrtf(ss), 1e-12f);
    v.x *= inv; v.y *= inv; v.z *= inv; v.w *= inv;
    {
        __half2 h0 = __floats2half2_rn(v.x, v.y), h1 = __floats2half2_rn(v.z, v.w);
        uint2 p; p.x = *reinterpret_cast<unsigned*>(&h0); p.y = *reinterpret_cast<unsigned*>(&h1);
        reinterpret_cast<uint2*>(g_relH + warp * 128)[lane] = p;
    }

#pragma unroll
    for (int c = 0; c < 4; c++) {
        const float* attn = (c < 2 ? attn_e : attn_r) + (c & 1) * (3 * DD);
        float4 wn = {0,0,0,0}, wr = {0,0,0,0};
        if (lane < D4) {
            wn = reinterpret_cast<const float4*>(attn + DD)[lane];
            wr = reinterpret_cast<const float4*>(attn + 2 * DD)[lane];
        }
        float dn = dot4(v, wn);
        float dr = dot4(v, wr);
        wred2(dn, dr);
        if (lane == 0) {
            int layer = c & 1;
            if (c < 2) { g_relsc[layer][warp].x = -2.f * dn; g_relsc[layer][warp].y = dr; }
            else       { g_relsc[layer][warp].z = -2.f * dn; g_relsc[layer][warp].w = dr; }
        }
    }
}

// ---------------- K2: initial means + tanh + ndot(0), 16-lane groups -------
__global__ void __launch_bounds__(256)
k_init(const int* __restrict__ src,
       const int* __restrict__ erel,
       const float* __restrict__ attn_e,
       const float* __restrict__ attn_r,
       float* __restrict__ out) {
    int warp = (blockIdx.x * blockDim.x + threadIdx.x) >> 5;
    int lane = threadIdx.x & 31;
    if (warp >= NN) return;
    int beg = g_row_ptr[warp], end = g_row_ptr[warp + 1];
    int len = end - beg;

    int gid = lane >> 4;
    int k   = lane & 15;

    float aE[8] = {0,0,0,0,0,0,0,0};
    float aR[8] = {0,0,0,0,0,0,0,0};

    int niter = (len + 1) >> 1;
    for (int it = 0; it < niter; it++) {
        int e = beg + 2 * it + gid;
        bool valid = e < end;
        int ec = valid ? e : end - 1;
        int s = src[ec], r = erel[ec];
        uint4 hE = reinterpret_cast<const uint4*>(g_entH + (size_t)s * 128)[k];
        uint4 hR = reinterpret_cast<const uint4*>(g_relEH + r * 128)[k];
        if (valid) {
            float fE[8], fR[8];
            h8f(hE, fE); h8f(hR, fR);
#pragma unroll
            for (int i = 0; i < 8; i++) { aE[i] += fE[i]; aR[i] += fR[i]; }
        }
    }

    // packed cross-group exchange: lane<16 keeps E totals, lane>=16 keeps R
    float aM[8];
#pragma unroll
    for (int i = 0; i < 8; i++) {
        float t = gid ? aE[i] : aR[i];
        t = __shfl_xor_sync(0xffffffffu, t, 16);
        aM[i] = (gid ? aR[i] : aE[i]) + t;
    }

    float inv = 1.f / (float)max(len, 1);
    float oM[8];
#pragma unroll
    for (int i = 0; i < 8; i++) oM[i] = tanhf(aM[i] * inv);

    {
        __half* row = g_featH0 + (size_t)warp * FH;
        reinterpret_cast<uint4*>(row)[gid * 16 + k] = f8h(oM);
    }
    {
        float4* out4 = reinterpret_cast<float4*>(out);
        size_t base = (size_t)warp * 150 + (gid ? 75 : 0);
        float4 lo = {oM[0], oM[1], oM[2], oM[3]};
        float4 hi = {oM[4], oM[5], oM[6], oM[7]};
        int f0 = 2 * k, f1 = 2 * k + 1;
        if (f0 < D4) __stcs(out4 + base + f0, lo);
        if (f1 < D4) __stcs(out4 + base + f1, hi);
    }
    {
        const float* wn = (gid ? attn_r : attn_e) + DD + 8 * k;
        float d = oM[0]*wn[0] + oM[1]*wn[1] + oM[2]*wn[2] + oM[3]*wn[3]
                + oM[4]*wn[4] + oM[5]*wn[5] + oM[6]*wn[6] + oM[7]*wn[7];
#pragma unroll
        for (int o = 1; o <= 8; o <<= 1) d += __shfl_xor_sync(0xffffffffu, d, o);
        float d16 = __shfl_xor_sync(0xffffffffu, d, 16);
        if (lane == 0) g_nd[0][warp] = make_float2(d, d16);
    }
}

// ---------------- K3: attention layer, fp16 gathers, split epilogue --------
template <int LAYER>
__global__ void __launch_bounds__(256)
k_layer(const int* __restrict__ src,
        const int* __restrict__ erel,
        const float* __restrict__ attn_e,
        const float* __restrict__ attn_r,
        float* __restrict__ out) {
    int warp = (blockIdx.x * blockDim.x + threadIdx.x) >> 5;
    int lane = threadIdx.x & 31;
    if (warp >= NN) return;
    int beg = g_row_ptr[warp], end = g_row_ptr[warp + 1];
    int len = end - beg;

    const __half* __restrict__ feat = (LAYER == 0) ? g_featH0 : g_featH1;
    const float2* __restrict__ nd   = g_nd[LAYER];
    const float4* __restrict__ rsc  = g_relsc[LAYER];

    int gid = lane >> 4;          // edge slot within pair
    int k   = lane & 15;          // half-chunk: dims [8k, 8k+8)

    float ZE = 0.f, ZR = 0.f;
    float accE[8] = {0,0,0,0,0,0,0,0};
    float accR[8] = {0,0,0,0,0,0,0,0};

    int niter = (len + 1) >> 1;
    for (int it = 0; it < niter; it++) {
        int e = beg + 2 * it + gid;
        bool valid = e < end;
        int ec = valid ? e : end - 1;
        int s = src[ec], r = erel[ec];

        const uint4* frow = reinterpret_cast<const uint4*>(feat + (size_t)s * FH);
        uint4 hE = frow[k];
        uint4 hR = frow[16 + k];
        uint4 hV = reinterpret_cast<const uint4*>(g_relH + r * 128)[k];
        float2 ndv = nd[s];
        float4 sc  = rsc[r];

        float fE[8], fR[8], rv[8];
        h8f(hE, fE); h8f(hR, fR); h8f(hV, rv);

        float pE = fE[0] * rv[0], pR = fR[0] * rv[0];
#pragma unroll
        for (int i = 1; i < 8; i++) {
            pE = fmaf(fE[i], rv[i], pE);
            pR = fmaf(fR[i], rv[i], pR);
        }
#pragma unroll
        for (int o = 1; o <= 8; o <<= 1) {
            pE += __shfl_xor_sync(0xffffffffu, pE, o);
            pR += __shfl_xor_sync(0xffffffffu, pR, o);
        }

        float wE = valid ? __expf(ndv.x + fmaf(pE, sc.x, sc.y)) : 0.f;
        float wR = valid ? __expf(ndv.y + fmaf(pR, sc.z, sc.w)) : 0.f;
        ZE += wE; ZR += wR;
        float bE = 2.f * wE * pE, bR = 2.f * wR * pR;

#pragma unroll
        for (int i = 0; i < 8; i++) {
            accE[i] = fmaf(wE, fE[i], fmaf(-bE, rv[i], accE[i]));
            accR[i] = fmaf(wR, fR[i], fmaf(-bR, rv[i], accR[i]));
        }
    }

    // split epilogue: packed cross-group exchange — lane<16 keeps full E sums,
    // lane>=16 keeps full R sums (each half-warp owns its output slice)
    float accM[8];
#pragma unroll
    for (int i = 0; i < 8; i++) {
        float t = gid ? accE[i] : accR[i];
        t = __shfl_xor_sync(0xffffffffu, t, 16);
        accM[i] = (gid ? accR[i] : accE[i]) + t;
    }
    float ZM;
    {
        float t = gid ? ZE : ZR;
        t = __shfl_xor_sync(0xffffffffu, t, 16);
        ZM = (gid ? ZR : ZE) + t;
    }

    float oM[8];
    if (len > 0) {
        float iz = 1.f / ZM;
#pragma unroll
        for (int i = 0; i < 8; i++) oM[i] = tanhf(accM[i] * iz);
    } else {
#pragma unroll
        for (int i = 0; i < 8; i++) oM[i] = 0.f;
    }

    // fp32 out store (own slice)
    {
        float4* out4 = reinterpret_cast<float4*>(out);
        size_t base = (size_t)warp * 150 + (LAYER + 1) * D4 + (gid ? 75 : 0);
        float4 lo = {oM[0], oM[1], oM[2], oM[3]};
        float4 hi = {oM[4], oM[5], oM[6], oM[7]};
        int f0 = 2 * k, f1 = 2 * k + 1;
        if (f0 < D4) __stcs(out4 + base + f0, lo);
        if (f1 < D4) __stcs(out4 + base + f1, hi);
    }

    if (LAYER == 0) {
        // fp16 feat1 store (own slice; padding dims are exact zeros)
        __half* row = g_featH1 + (size_t)warp * FH;
        reinterpret_cast<uint4*>(row)[gid * 16 + k] = f8h(oM);

        // ndot layer 1, split by half-warp: lane<16 E·wnE, lane>=16 R·wnR
        const float* wn = (gid ? attn_r : attn_e) + 3 * DD + DD + 8 * k;
        float d = oM[0]*wn[0] + oM[1]*wn[1] + oM[2]*wn[2] + oM[3]*wn[3]
                + oM[4]*wn[4] + oM[5]*wn[5] + oM[6]*wn[6] + oM[7]*wn[7];
#pragma unroll
        for (int o = 1; o <= 8; o <<= 1) d += __shfl_xor_sync(0xffffffffu, d, o);
        float d16 = __shfl_xor_sync(0xffffffffu, d, 16);  // other half's total
        if (lane == 0) g_nd[1][warp] = make_float2(d, d16);
    }
}

// ---------------------------------------------------------------------------
extern "C" void kernel_launch(void* const* d_in, const int* in_sizes, int n_in,
                              void* d_out, int out_size) {
    const float* ent_emb = (const float*)d_in[0];
    const float* rel_emb = (const float*)d_in[1];
    const float* attn_e  = (const float*)d_in[2];
    const float* attn_r  = (const float*)d_in[3];
    const int*   src     = (const int*)d_in[4];
    const int*   dst     = (const int*)d_in[5];
    const int*   erel    = (const int*)d_in[6];
    float* out = (float*)d_out;

    k_rowptr<<<(NN + 1 + 255) / 256, 256>>>(dst);
    k_cvt<<<((NN + RR) * 32 + 255) / 256, 256>>>(ent_emb, rel_emb);
    k_rel<<<(RR * 32 + 255) / 256, 256>>>(rel_emb, attn_e, attn_r);
    k_init<<<(NN * 32) / 256, 256>>>(src, erel, attn_e, attn_r, out);
    k_layer<0><<<(NN * 32) / 256, 256>>>(src, erel, attn_e, attn_r, out);
    k_layer<1><<<(NN * 32) / 256, 256>>>(src, erel, attn_e, attn_r, out);
}